// round 6
// baseline (speedup 1.0000x reference)
#include <cuda_runtime.h>
#include <cstdint>

#define T_STEPS 2048
#define HID 64
#define EPB 7
#define NTHR 512
#define QS (EPB * HID)          // 448

typedef unsigned long long u64;

// ---------- f32x2 packed math ----------
__device__ __forceinline__ u64 fma2(u64 a, u64 b, u64 c) {
    u64 d; asm("fma.rn.f32x2 %0, %1, %2, %3;" : "=l"(d) : "l"(a), "l"(b), "l"(c)); return d;
}
__device__ __forceinline__ u64 add2(u64 a, u64 b) {
    u64 d; asm("add.rn.f32x2 %0, %1, %2;" : "=l"(d) : "l"(a), "l"(b)); return d;
}
__device__ __forceinline__ u64 pack2(float lo, float hi) {
    u64 d; asm("mov.b64 %0, {%1, %2};" : "=l"(d) : "f"(lo), "f"(hi)); return d;
}
__device__ __forceinline__ float2 unpack2(u64 v) {
    float a, b; asm("mov.b64 {%0, %1}, %2;" : "=f"(a), "=f"(b) : "l"(v));
    return make_float2(a, b);
}
__device__ __forceinline__ u64 shfl_xor64(u64 v, int m) {
    float2 p = unpack2(v);
    p.x = __shfl_xor_sync(0xFFFFFFFFu, p.x, m);
    p.y = __shfl_xor_sync(0xFFFFFFFFu, p.y, m);
    return pack2(p.x, p.y);
}

// ---------- activations (EX2+RCP; same numerics class as prior rounds) ----------
__device__ __forceinline__ float sig_(float x) {
    return __fdividef(1.0f, 1.0f + __expf(-x));
}
__device__ __forceinline__ float tanhx_(float x) {
    return __fdividef(2.0f, 1.0f + __expf(-2.0f * x)) - 1.0f;
}

extern __shared__ float smem_f[];
// SMEM layout (float offsets)
#define OX   0                       // x: [EPB][T_STEPS]          14336
#define OH1  (EPB * T_STEPS)         // h1: [2][EPB][HID]          896
#define OH2  (OH1 + 2 * QS)          // h2: [2][EPB][HID]          896
#define OG   (OH2 + 2 * QS)          // gather: [16 warps][2][7][4][4] = 3584
#define SMEM_FLOATS (OG + 16 * 224)  // 19712 floats = 78848 B

__global__ void __launch_bounds__(NTHR, 1)
lstm_fused(const float* __restrict__ x,
           const float* __restrict__ Wih0, const float* __restrict__ Whh0,
           const float* __restrict__ bih0, const float* __restrict__ bhh0,
           const float* __restrict__ Wih1, const float* __restrict__ Whh1,
           const float* __restrict__ bih1, const float* __restrict__ bhh1,
           const float* __restrict__ fcW,  const float* __restrict__ fcb,
           float* __restrict__ out, int B)
{
    float* xs  = smem_f + OX;
    float* h1f = smem_f + OH1;
    float* h2f = smem_f + OH2;
    float* gsh = smem_f + OG;

    const int tid  = threadIdx.x;
    const int w    = tid >> 5;           // warp 0..15
    const int lane = tid & 31;
    const int uo   = lane >> 3;          // unit-within-warp 0..3
    const int s    = lane & 7;           // k-split 0..7
    const int u    = w * 4 + uo;         // hidden unit 0..63
    const int g    = s >> 1;             // this lane's gate after reduce-scatter
    const int b0e  = blockIdx.x * EPB;

    // activation-lane mapping: lane < 28 owns cell (ae, au)
    const int ae  = lane >> 2;
    const int au  = w * 4 + (lane & 3);
    const bool actv = (lane < 28);

    // ---- stage x rows ----
    for (int i = tid; i < EPB * T_STEPS / 4; i += NTHR) {
        int e = i / (T_STEPS / 4), c = i % (T_STEPS / 4);
        int be = b0e + e; if (be > B - 1) be = B - 1;
        ((float4*)xs)[i] = ((const float4*)(x + (size_t)be * T_STEPS))[c];
    }
    for (int i = tid; i < 4 * QS; i += NTHR) { (i < 2 * QS ? h1f : h2f)[i & (2 * QS - 1)] = 0.0f; }

    // ---- register weights: strided k-pairs (lane s owns pair-indices 8p+s) ----
    u64 w0[4][4];    // layer0: gate x p,  K=64  -> 32 pairs
    u64 w1[4][8];    // layer1: gate x p,  K=128 -> 64 pairs (first 32 Wih1, last 32 Whh1)
#pragma unroll
    for (int gg = 0; gg < 4; ++gg) {
        const int row = gg * 64 + u;
#pragma unroll
        for (int p = 0; p < 4; ++p)
            w0[gg][p] = ((const u64*)Whh0)[row * 32 + 8 * p + s];
#pragma unroll
        for (int p = 0; p < 4; ++p)
            w1[gg][p] = ((const u64*)Wih1)[row * 32 + 8 * p + s];
#pragma unroll
        for (int p = 4; p < 8; ++p)
            w1[gg][p] = ((const u64*)Whh1)[row * 32 + 8 * (p - 4) + s];
    }
    // per-lane bias (for its gate) + x-weight
    const float bias0 = bih0[g * 64 + u] + bhh0[g * 64 + u];
    const float bias1 = bih1[g * 64 + u] + bhh1[g * 64 + u];
    const float xw0   = Wih0[g * 64 + u];

    float* gw = gsh + w * 224;           // per-warp gather: [2][7][4 uo][4 gate]
    float cL0 = 0.0f, cL1 = 0.0f;
    __syncthreads();

#pragma unroll 1
    for (int j = 0; j <= T_STEPS; ++j) {
        const int rb = j & 1;
        const int wb = rb ^ 1;

        // ============ phase 1: partials + in-warp reduce-scatter ============
        if (j < T_STEPS) {   // layer0 for step j (reads h1[j-1])
            const u64* hb = (const u64*)(h1f + rb * QS);
#pragma unroll
            for (int e = 0; e < EPB; ++e) {
                const u64* hv = hb + e * 32;
                u64 v0 = hv[s], v1 = hv[8 + s], v2 = hv[16 + s], v3 = hv[24 + s];
                u64 a0 = fma2(v0, w0[0][0], fma2(v1, w0[0][1], fma2(v2, w0[0][2], fma2(v3, w0[0][3], 0ULL))));
                u64 a1 = fma2(v0, w0[1][0], fma2(v1, w0[1][1], fma2(v2, w0[1][2], fma2(v3, w0[1][3], 0ULL))));
                u64 a2 = fma2(v0, w0[2][0], fma2(v1, w0[2][1], fma2(v2, w0[2][2], fma2(v3, w0[2][3], 0ULL))));
                u64 a3 = fma2(v0, w0[3][0], fma2(v1, w0[3][1], fma2(v2, w0[3][2], fma2(v3, w0[3][3], 0ULL))));
                float2 r0 = unpack2(a0), r1 = unpack2(a1), r2 = unpack2(a2), r3 = unpack2(a3);
                u64 uIF = pack2(r0.x + r0.y, r1.x + r1.y);
                u64 uGO = pack2(r2.x + r2.y, r3.x + r3.y);
                u64 keep = (s & 4) ? uGO : uIF;
                u64 send = (s & 4) ? uIF : uGO;
                keep = add2(keep, shfl_xor64(send, 4));
                float2 kp = unpack2(keep);
                float k1 = (s & 2) ? kp.y : kp.x;
                float sd = (s & 2) ? kp.x : kp.y;
                k1 += __shfl_xor_sync(0xFFFFFFFFu, sd, 2);
                k1 += __shfl_xor_sync(0xFFFFFFFFu, k1, 1);
                float xv = xs[e * T_STEPS + j];
                k1 += xv * xw0 + bias0;
                if (!(s & 1)) gw[e * 16 + uo * 4 + g] = k1;
            }
        }
        if (j > 0) {         // layer1 for step j-1 (reads h1[j-1], h2[j-2])
            const u64* hb1 = (const u64*)(h1f + rb * QS);
            const u64* hb2 = (const u64*)(h2f + rb * QS);
#pragma unroll
            for (int e = 0; e < EPB; ++e) {
                const u64* hv1 = hb1 + e * 32;
                const u64* hv2 = hb2 + e * 32;
                u64 v0 = hv1[s], v1 = hv1[8 + s], v2 = hv1[16 + s], v3 = hv1[24 + s];
                u64 v4 = hv2[s], v5 = hv2[8 + s], v6 = hv2[16 + s], v7 = hv2[24 + s];
                u64 a0 = fma2(v0, w1[0][0], fma2(v1, w1[0][1], fma2(v2, w1[0][2], fma2(v3, w1[0][3], 0ULL))));
                u64 a1 = fma2(v0, w1[1][0], fma2(v1, w1[1][1], fma2(v2, w1[1][2], fma2(v3, w1[1][3], 0ULL))));
                u64 a2 = fma2(v0, w1[2][0], fma2(v1, w1[2][1], fma2(v2, w1[2][2], fma2(v3, w1[2][3], 0ULL))));
                u64 a3 = fma2(v0, w1[3][0], fma2(v1, w1[3][1], fma2(v2, w1[3][2], fma2(v3, w1[3][3], 0ULL))));
                a0 = fma2(v4, w1[0][4], fma2(v5, w1[0][5], fma2(v6, w1[0][6], fma2(v7, w1[0][7], a0))));
                a1 = fma2(v4, w1[1][4], fma2(v5, w1[1][5], fma2(v6, w1[1][6], fma2(v7, w1[1][7], a1))));
                a2 = fma2(v4, w1[2][4], fma2(v5, w1[2][5], fma2(v6, w1[2][6], fma2(v7, w1[2][7], a2))));
                a3 = fma2(v4, w1[3][4], fma2(v5, w1[3][5], fma2(v6, w1[3][6], fma2(v7, w1[3][7], a3))));
                float2 r0 = unpack2(a0), r1 = unpack2(a1), r2 = unpack2(a2), r3 = unpack2(a3);
                u64 uIF = pack2(r0.x + r0.y, r1.x + r1.y);
                u64 uGO = pack2(r2.x + r2.y, r3.x + r3.y);
                u64 keep = (s & 4) ? uGO : uIF;
                u64 send = (s & 4) ? uIF : uGO;
                keep = add2(keep, shfl_xor64(send, 4));
                float2 kp = unpack2(keep);
                float k1 = (s & 2) ? kp.y : kp.x;
                float sd = (s & 2) ? kp.x : kp.y;
                k1 += __shfl_xor_sync(0xFFFFFFFFu, sd, 2);
                k1 += __shfl_xor_sync(0xFFFFFFFFu, k1, 1);
                k1 += bias1;
                if (!(s & 1)) gw[112 + e * 16 + uo * 4 + g] = k1;
            }
        }
        __syncwarp();

        // ============ phase 2: one lane = one full LSTM cell ============
        if (actv) {
            if (j < T_STEPS) {
                float4 g4 = *(const float4*)(gw + ae * 16 + (au & 3) * 4);
                float gi = sig_(g4.x), gf = sig_(g4.y);
                float gg = tanhx_(g4.z), go = sig_(g4.w);
                cL0 = gf * cL0 + gi * gg;
                h1f[wb * QS + ae * HID + au] = go * tanhx_(cL0);
            }
            if (j > 0) {
                float4 g4 = *(const float4*)(gw + 112 + ae * 16 + (au & 3) * 4);
                float gi = sig_(g4.x), gf = sig_(g4.y);
                float gg = tanhx_(g4.z), go = sig_(g4.w);
                cL1 = gf * cL1 + gi * gg;
                h2f[wb * QS + ae * HID + au] = go * tanhx_(cL1);
            }
        }
        __syncthreads();
    }

    // ---- final FC: h2[T-1] is in slot 1 ----
    if (tid < EPB * 32) {
        const int e = tid >> 5, lane2 = tid & 31;
        const float* h2l = h2f + (1 * EPB + e) * HID;
        float acc = h2l[lane2] * fcW[lane2] + h2l[32 + lane2] * fcW[32 + lane2];
#pragma unroll
        for (int o = 16; o > 0; o >>= 1)
            acc += __shfl_down_sync(0xFFFFFFFFu, acc, o);
        if (lane2 == 0) {
            int be = b0e + e; if (be > B - 1) be = B - 1;
            out[be] = acc + fcb[0];
        }
    }
}

extern "C" void kernel_launch(void* const* d_in, const int* in_sizes, int n_in,
                              void* d_out, int out_size)
{
    const float* x    = (const float*)d_in[0];
    const float* Wih0 = (const float*)d_in[1];
    const float* Whh0 = (const float*)d_in[2];
    const float* bih0 = (const float*)d_in[3];
    const float* bhh0 = (const float*)d_in[4];
    const float* Wih1 = (const float*)d_in[5];
    const float* Whh1 = (const float*)d_in[6];
    const float* bih1 = (const float*)d_in[7];
    const float* bhh1 = (const float*)d_in[8];
    const float* fcW  = (const float*)d_in[9];
    const float* fcb  = (const float*)d_in[10];
    float* out = (float*)d_out;

    int B = in_sizes[0] / T_STEPS;
    if (B < 1) B = 1;
    int blocks = (B + EPB - 1) / EPB;

    const int smem_bytes = SMEM_FLOATS * 4;
    cudaFuncSetAttribute(lstm_fused, cudaFuncAttributeMaxDynamicSharedMemorySize,
                         smem_bytes);

    lstm_fused<<<blocks, NTHR, smem_bytes>>>(x, Wih0, Whh0, bih0, bhh0,
                                             Wih1, Whh1, bih1, bhh1,
                                             fcW, fcb, out, B);
}